// round 1
// baseline (speedup 1.0000x reference)
#include <cuda_runtime.h>
#include <cstdint>
#include <cstddef>

// ---------------------------------------------------------------------------
// Dual cross-attention (e2s, s2e), tf32 mma.sync implementation.
//   s2e = softmax( (skel Wq_s2e^T)(sens Wk_e^T)^T * s, mask_sens ) (sens Wv_e^T) Wo_e^T
//   e2s = softmax( (sens Wq_e2s^T)(skel Wk_s^T)^T * s, mask_skel ) (skel Wv_s^T) Wo_s^T
// Output: d_out = [ e2s (4*2048*512) | s2e (4*2048*512) ]  (tuple order)
// ---------------------------------------------------------------------------

constexpr int kB = 4;
constexpr int kT = 2048;
constexpr int kD = 512;
constexpr int kH = 8;
constexpr int kDK = 64;
constexpr int kM = kB * kT;  // 8192 rows
constexpr float kSmScale = 1.5f / 8.0f;             // SCALE / sqrt(DK)
constexpr float kLog2e = 1.4426950408889634f;

// Scratch (allocation-free rule: __device__ globals). 4 x 16 MB.
__device__ float g_Q[(size_t)kM * kD];
__device__ float g_K[(size_t)kM * kD];
__device__ float g_V[(size_t)kM * kD];
__device__ float g_O[(size_t)kM * kD];

__device__ __forceinline__ uint32_t f2tf(float f) {
  uint32_t u;
  asm("cvt.rna.tf32.f32 %0, %1;" : "=r"(u) : "f"(f));
  return u;
}

// D += A(16x8, row) * B(8x8, col), tf32 in, fp32 accum.
__device__ __forceinline__ void mma8(float* d, const uint32_t* a, uint32_t b0,
                                     uint32_t b1) {
  asm volatile(
      "mma.sync.aligned.m16n8k8.row.col.f32.tf32.tf32.f32 "
      "{%0,%1,%2,%3}, {%4,%5,%6,%7}, {%8,%9}, {%0,%1,%2,%3};\n"
      : "+f"(d[0]), "+f"(d[1]), "+f"(d[2]), "+f"(d[3])
      : "r"(a[0]), "r"(a[1]), "r"(a[2]), "r"(a[3]), "r"(b0), "r"(b1));
}

// ---------------------------------------------------------------------------
// C[8192,512] = A[8192,512] @ W[512,512]^T   (all row-major, K contiguous)
// CTA tile 128x128, K-tile 32. 8 warps = 4(M) x 2(N), warp tile 32x64.
// ---------------------------------------------------------------------------
__global__ void __launch_bounds__(256, 2)
    gemm_nt_tf32(const float* __restrict__ A, const float* __restrict__ W,
                 float* __restrict__ C) {
  __shared__ uint32_t sA[128][36];  // pad 36: bank = (4*row+col)%32, conflict-free
  __shared__ uint32_t sB[128][36];

  const int tid = threadIdx.x;
  const int lane = tid & 31;
  const int wid = tid >> 5;
  const int wm = wid & 3;
  const int wn = wid >> 2;
  const int g = lane >> 2;   // 0..7
  const int tg = lane & 3;   // 0..3
  const int m0 = blockIdx.x * 128;
  const int n0 = blockIdx.y * 128;

  float acc[2][8][4];
#pragma unroll
  for (int mi = 0; mi < 2; ++mi)
#pragma unroll
    for (int ni = 0; ni < 8; ++ni)
#pragma unroll
      for (int c = 0; c < 4; ++c) acc[mi][ni][c] = 0.f;

  const int lrow = tid >> 3;        // 0..31
  const int lcol = (tid & 7) * 4;   // 0..28

  for (int k0 = 0; k0 < kD; k0 += 32) {
    __syncthreads();
#pragma unroll
    for (int r = 0; r < 4; ++r) {
      int row = lrow + r * 32;
      float4 va = *reinterpret_cast<const float4*>(
          A + (size_t)(m0 + row) * kD + k0 + lcol);
      sA[row][lcol + 0] = f2tf(va.x);
      sA[row][lcol + 1] = f2tf(va.y);
      sA[row][lcol + 2] = f2tf(va.z);
      sA[row][lcol + 3] = f2tf(va.w);
      float4 vb = *reinterpret_cast<const float4*>(
          W + (size_t)(n0 + row) * kD + k0 + lcol);
      sB[row][lcol + 0] = f2tf(vb.x);
      sB[row][lcol + 1] = f2tf(vb.y);
      sB[row][lcol + 2] = f2tf(vb.z);
      sB[row][lcol + 3] = f2tf(vb.w);
    }
    __syncthreads();
#pragma unroll
    for (int kk = 0; kk < 4; ++kk) {
      uint32_t a[2][4];
#pragma unroll
      for (int mi = 0; mi < 2; ++mi) {
        int rb = wm * 32 + mi * 16;
        a[mi][0] = sA[rb + g][kk * 8 + tg];
        a[mi][1] = sA[rb + g + 8][kk * 8 + tg];
        a[mi][2] = sA[rb + g][kk * 8 + tg + 4];
        a[mi][3] = sA[rb + g + 8][kk * 8 + tg + 4];
      }
      uint32_t bf[8][2];
#pragma unroll
      for (int ni = 0; ni < 8; ++ni) {
        int rb = wn * 64 + ni * 8 + g;
        bf[ni][0] = sB[rb][kk * 8 + tg];
        bf[ni][1] = sB[rb][kk * 8 + tg + 4];
      }
#pragma unroll
      for (int mi = 0; mi < 2; ++mi)
#pragma unroll
        for (int ni = 0; ni < 8; ++ni)
          mma8(acc[mi][ni], a[mi], bf[ni][0], bf[ni][1]);
    }
  }

#pragma unroll
  for (int mi = 0; mi < 2; ++mi) {
    int row = m0 + wm * 32 + mi * 16 + g;
#pragma unroll
    for (int ni = 0; ni < 8; ++ni) {
      int col = n0 + wn * 64 + ni * 8 + 2 * tg;
      float2 v0 = make_float2(acc[mi][ni][0], acc[mi][ni][1]);
      float2 v1 = make_float2(acc[mi][ni][2], acc[mi][ni][3]);
      *reinterpret_cast<float2*>(C + (size_t)row * kD + col) = v0;
      *reinterpret_cast<float2*>(C + (size_t)(row + 8) * kD + col) = v1;
    }
  }
}

// ---------------------------------------------------------------------------
// Flash attention, one CTA per (64-query tile, head, batch). 4 warps x 16 rows.
// Q/K/V laid out [B*T, 512] with head h at columns h*64..h*64+63.
// Online softmax kept in exp2 domain (scale folded with log2e); mask as
// additive bias -1e30*log2e (degenerate all-masked row reduces to uniform,
// matching the reference exactly).
// ---------------------------------------------------------------------------
__global__ void __launch_bounds__(128)
    attn_tf32(const float* __restrict__ Qg, const float* __restrict__ Kg,
              const float* __restrict__ Vg, const int* __restrict__ mask,
              float* __restrict__ Og) {
  __shared__ uint32_t sK[64][68];  // also reused for Q staging and P tiles
  __shared__ uint32_t sV[64][72];  // pad 72: (8*k+d)%32 conflict-free B-frags
  __shared__ float sBias[64];

  const int tid = threadIdx.x;
  const int lane = tid & 31;
  const int w = tid >> 5;
  const int g = lane >> 2;
  const int tg = lane & 3;
  const int bb = blockIdx.z;
  const int h = blockIdx.y;
  const int q0 = blockIdx.x * 64;
  const int colh = h * kDK;
  const size_t qrow0 = (size_t)bb * kT + q0;
  const size_t kvrow0 = (size_t)bb * kT;
  const int w16 = w * 16;

  const int lr = tid >> 4;        // 0..7
  const int lc = (tid & 15) * 4;  // 0..60

  // ---- stage Q tile (64x64) into sK, then lift to register A-fragments ----
#pragma unroll
  for (int r = 0; r < 8; ++r) {
    int row = lr + r * 8;
    float4 v = *reinterpret_cast<const float4*>(
        Qg + (qrow0 + row) * kD + colh + lc);
    sK[row][lc + 0] = f2tf(v.x);
    sK[row][lc + 1] = f2tf(v.y);
    sK[row][lc + 2] = f2tf(v.z);
    sK[row][lc + 3] = f2tf(v.w);
  }
  __syncthreads();

  uint32_t aq[8][4];
#pragma unroll
  for (int kk = 0; kk < 8; ++kk) {
    aq[kk][0] = sK[w16 + g][kk * 8 + tg];
    aq[kk][1] = sK[w16 + g + 8][kk * 8 + tg];
    aq[kk][2] = sK[w16 + g][kk * 8 + tg + 4];
    aq[kk][3] = sK[w16 + g + 8][kk * 8 + tg + 4];
  }

  float o[8][4];
#pragma unroll
  for (int ni = 0; ni < 8; ++ni)
#pragma unroll
    for (int c = 0; c < 4; ++c) o[ni][c] = 0.f;
  float mrow0 = -INFINITY, mrow1 = -INFINITY;
  float l0 = 0.f, l1 = 0.f;
  const float sc = kSmScale * kLog2e;

  for (int j0 = 0; j0 < kT; j0 += 64) {
    __syncthreads();  // previous chunk's PV done; safe to overwrite sK/sV
#pragma unroll
    for (int r = 0; r < 8; ++r) {
      int row = lr + r * 8;
      size_t goff = (kvrow0 + j0 + row) * kD + colh + lc;
      float4 vk = *reinterpret_cast<const float4*>(Kg + goff);
      sK[row][lc + 0] = f2tf(vk.x);
      sK[row][lc + 1] = f2tf(vk.y);
      sK[row][lc + 2] = f2tf(vk.z);
      sK[row][lc + 3] = f2tf(vk.w);
      float4 vv = *reinterpret_cast<const float4*>(Vg + goff);
      sV[row][lc + 0] = f2tf(vv.x);
      sV[row][lc + 1] = f2tf(vv.y);
      sV[row][lc + 2] = f2tf(vv.z);
      sV[row][lc + 3] = f2tf(vv.w);
    }
    if (tid < 64)
      sBias[tid] = mask[kvrow0 + j0 + tid] ? 0.f : -1.4426950e30f;
    __syncthreads();

    // ---- S = Q K^T (16 rows x 64 keys per warp) ----
    float s[8][4];
#pragma unroll
    for (int ni = 0; ni < 8; ++ni)
#pragma unroll
      for (int c = 0; c < 4; ++c) s[ni][c] = 0.f;
#pragma unroll
    for (int kk = 0; kk < 8; ++kk)
#pragma unroll
      for (int ni = 0; ni < 8; ++ni) {
        uint32_t b0 = sK[ni * 8 + g][kk * 8 + tg];
        uint32_t b1 = sK[ni * 8 + g][kk * 8 + tg + 4];
        mma8(s[ni], aq[kk], b0, b1);
      }

    // ---- scale + mask bias, row max (quad-owned rows g and g+8) ----
    float mx0 = -INFINITY, mx1 = -INFINITY;
#pragma unroll
    for (int ni = 0; ni < 8; ++ni) {
      float bb0 = sBias[ni * 8 + 2 * tg];
      float bb1 = sBias[ni * 8 + 2 * tg + 1];
      s[ni][0] = s[ni][0] * sc + bb0;
      s[ni][1] = s[ni][1] * sc + bb1;
      s[ni][2] = s[ni][2] * sc + bb0;
      s[ni][3] = s[ni][3] * sc + bb1;
      mx0 = fmaxf(mx0, fmaxf(s[ni][0], s[ni][1]));
      mx1 = fmaxf(mx1, fmaxf(s[ni][2], s[ni][3]));
    }
    mx0 = fmaxf(mx0, __shfl_xor_sync(0xffffffffu, mx0, 1));
    mx0 = fmaxf(mx0, __shfl_xor_sync(0xffffffffu, mx0, 2));
    mx1 = fmaxf(mx1, __shfl_xor_sync(0xffffffffu, mx1, 1));
    mx1 = fmaxf(mx1, __shfl_xor_sync(0xffffffffu, mx1, 2));
    float mn0 = fmaxf(mrow0, mx0);
    float mn1 = fmaxf(mrow1, mx1);
    float al0 = exp2f(mrow0 - mn0);
    float al1 = exp2f(mrow1 - mn1);
    mrow0 = mn0;
    mrow1 = mn1;

    __syncthreads();  // all warps done reading sK -> reuse rows as P

    float rs0 = 0.f, rs1 = 0.f;
#pragma unroll
    for (int ni = 0; ni < 8; ++ni) {
      float p0 = exp2f(s[ni][0] - mn0);
      float p1 = exp2f(s[ni][1] - mn0);
      float p2 = exp2f(s[ni][2] - mn1);
      float p3 = exp2f(s[ni][3] - mn1);
      rs0 += p0 + p1;
      rs1 += p2 + p3;
      int col = ni * 8 + 2 * tg;
      sK[w16 + g][col] = f2tf(p0);
      sK[w16 + g][col + 1] = f2tf(p1);
      sK[w16 + g + 8][col] = f2tf(p2);
      sK[w16 + g + 8][col + 1] = f2tf(p3);
    }
    rs0 += __shfl_xor_sync(0xffffffffu, rs0, 1);
    rs0 += __shfl_xor_sync(0xffffffffu, rs0, 2);
    rs1 += __shfl_xor_sync(0xffffffffu, rs1, 1);
    rs1 += __shfl_xor_sync(0xffffffffu, rs1, 2);
    l0 = l0 * al0 + rs0;
    l1 = l1 * al1 + rs1;
#pragma unroll
    for (int ni = 0; ni < 8; ++ni) {
      o[ni][0] *= al0;
      o[ni][1] *= al0;
      o[ni][2] *= al1;
      o[ni][3] *= al1;
    }
    __syncwarp();  // P visible to own warp's lanes

    // ---- O += P V ----
#pragma unroll
    for (int kk = 0; kk < 8; ++kk) {
      uint32_t pa[4];
      pa[0] = sK[w16 + g][kk * 8 + tg];
      pa[1] = sK[w16 + g + 8][kk * 8 + tg];
      pa[2] = sK[w16 + g][kk * 8 + tg + 4];
      pa[3] = sK[w16 + g + 8][kk * 8 + tg + 4];
#pragma unroll
      for (int ni = 0; ni < 8; ++ni) {
        uint32_t b0 = sV[kk * 8 + tg][ni * 8 + g];
        uint32_t b1 = sV[kk * 8 + tg + 4][ni * 8 + g];
        mma8(o[ni], pa, b0, b1);
      }
    }
  }

  const float inv0 = 1.f / l0;
  const float inv1 = 1.f / l1;
#pragma unroll
  for (int ni = 0; ni < 8; ++ni) {
    int col = colh + ni * 8 + 2 * tg;
    float2 v0 = make_float2(o[ni][0] * inv0, o[ni][1] * inv0);
    float2 v1 = make_float2(o[ni][2] * inv1, o[ni][3] * inv1);
    *reinterpret_cast<float2*>(Og + (qrow0 + w16 + g) * kD + col) = v0;
    *reinterpret_cast<float2*>(Og + (qrow0 + w16 + g + 8) * kD + col) = v1;
  }
}

// ---------------------------------------------------------------------------
extern "C" void kernel_launch(void* const* d_in, const int* in_sizes, int n_in,
                              void* d_out, int out_size) {
  const float* skel = (const float*)d_in[0];
  const float* sens = (const float*)d_in[1];
  const int* mask_skel = (const int*)d_in[2];
  const int* mask_sens = (const int*)d_in[3];
  const float* Wq_s2e = (const float*)d_in[4];
  const float* Wk_e = (const float*)d_in[5];
  const float* Wv_e = (const float*)d_in[6];
  const float* Wq_e2s = (const float*)d_in[7];
  const float* Wk_s = (const float*)d_in[8];
  const float* Wv_s = (const float*)d_in[9];
  const float* Wo_s = (const float*)d_in[10];
  const float* Wo_e = (const float*)d_in[11];

  float* out_e2s = (float*)d_out;                       // tuple element 0
  float* out_s2e = (float*)d_out + (size_t)kM * kD;     // tuple element 1

  float *Qp, *Kp, *Vp, *Op;
  cudaGetSymbolAddress((void**)&Qp, g_Q);
  cudaGetSymbolAddress((void**)&Kp, g_K);
  cudaGetSymbolAddress((void**)&Vp, g_V);
  cudaGetSymbolAddress((void**)&Op, g_O);

  dim3 ggrid(kM / 128, kD / 128);   // 64 x 4
  dim3 agrid(kT / 64, kH, kB);      // 32 x 8 x 4

  // ---- s2e: skel queries attend over sensor K/V ----
  gemm_nt_tf32<<<ggrid, 256>>>(skel, Wq_s2e, Qp);
  gemm_nt_tf32<<<ggrid, 256>>>(sens, Wk_e, Kp);
  gemm_nt_tf32<<<ggrid, 256>>>(sens, Wv_e, Vp);
  attn_tf32<<<agrid, 128>>>(Qp, Kp, Vp, mask_sens, Op);
  gemm_nt_tf32<<<ggrid, 256>>>(Op, Wo_e, out_s2e);

  // ---- e2s: sensor queries attend over skeleton K/V ----
  gemm_nt_tf32<<<ggrid, 256>>>(sens, Wq_e2s, Qp);
  gemm_nt_tf32<<<ggrid, 256>>>(skel, Wk_s, Kp);
  gemm_nt_tf32<<<ggrid, 256>>>(skel, Wv_s, Vp);
  attn_tf32<<<agrid, 128>>>(Qp, Kp, Vp, mask_skel, Op);
  gemm_nt_tf32<<<ggrid, 256>>>(Op, Wo_s, out_e2s);
}